// round 2
// baseline (speedup 1.0000x reference)
#include <cuda_runtime.h>

// Problem constants (fixed by the dataset)
#define BATCH   2048
#define LATD    32
#define HID     256
#define DIM     20
#define TSTEPS  512

#define ROWS    16                 // batch rows per CTA
#define RP      18                 // padded SMEM row stride (2-way write conflicts only)
#define NCTA    (BATCH / ROWS)     // 128 CTAs
#define NT      256                // threads per CTA (1 thread = 1 hidden unit)

// ---------------- packed fp32x2 helpers (Blackwell f32x2 pipe) ----------------
__device__ __forceinline__ unsigned long long dup2(float w) {
    unsigned long long d;
    asm("mov.b64 %0, {%1, %1};" : "=l"(d) : "f"(w));
    return d;
}
__device__ __forceinline__ unsigned long long fma2(unsigned long long a,
                                                   unsigned long long b,
                                                   unsigned long long c) {
    unsigned long long d;
    asm("fma.rn.f32x2 %0, %1, %2, %3;" : "=l"(d) : "l"(a), "l"(b), "l"(c));
    return d;
}
__device__ __forceinline__ float2 unpack2(unsigned long long v) {
    float2 f;
    asm("mov.b64 {%0, %1}, %2;" : "=f"(f.x), "=f"(f.y) : "l"(v));
    return f;
}

// ---------------- saturation-safe fast transcendentals ----------------
__device__ __forceinline__ float sigm(float x) {
    // x->-inf: expf(-x)=inf -> 1/inf = 0 ; x->+inf: 1/(1+0)=1. No NaN paths.
    return __fdividef(1.f, 1.f + __expf(-x));
}
__device__ __forceinline__ float tanh_(float x) {
    // tanh(x) = 1 - 2/(e^{2x}+1); e=inf -> 1 ; e=0 -> -1. No NaN paths.
    float e = __expf(2.f * x);
    return 1.f - __fdividef(2.f, e + 1.f);
}

// ---------------- gate GEMM: acc[g][rp] += W[g*HID+tid, k] * hs[k][2rp..2rp+1] ----------------
template <int K>
__device__ __forceinline__ void gemm_gates(const float* __restrict__ w,
                                           const float* __restrict__ hs,
                                           int tid,
                                           unsigned long long (&acc)[4][8]) {
    const float* w0 = w + (size_t)(0 * HID + tid) * K;
    const float* w1 = w + (size_t)(1 * HID + tid) * K;
    const float* w2 = w + (size_t)(2 * HID + tid) * K;
    const float* w3 = w + (size_t)(3 * HID + tid) * K;
    #pragma unroll 2
    for (int k4 = 0; k4 < K / 4; ++k4) {
        float4 a0 = __ldg(reinterpret_cast<const float4*>(w0) + k4);
        float4 a1 = __ldg(reinterpret_cast<const float4*>(w1) + k4);
        float4 a2 = __ldg(reinterpret_cast<const float4*>(w2) + k4);
        float4 a3 = __ldg(reinterpret_cast<const float4*>(w3) + k4);
        float wk[4][4] = {{a0.x, a0.y, a0.z, a0.w},
                          {a1.x, a1.y, a1.z, a1.w},
                          {a2.x, a2.y, a2.z, a2.w},
                          {a3.x, a3.y, a3.z, a3.w}};
        #pragma unroll
        for (int kk = 0; kk < 4; ++kk) {
            const float* hp = hs + (4 * k4 + kk) * RP;
            unsigned long long h2[8];
            #pragma unroll
            for (int rp = 0; rp < 8; ++rp)
                h2[rp] = *reinterpret_cast<const unsigned long long*>(hp + 2 * rp);
            #pragma unroll
            for (int g = 0; g < 4; ++g) {
                unsigned long long wd = dup2(wk[g][kk]);
                #pragma unroll
                for (int rp = 0; rp < 8; ++rp)
                    acc[g][rp] = fma2(h2[rp], wd, acc[g][rp]);
            }
        }
    }
}

__device__ __forceinline__ void cell_update(unsigned long long (&acc)[4][8],
                                            float (&c)[ROWS], float (&hnew)[ROWS]) {
    #pragma unroll
    for (int rp = 0; rp < 8; ++rp) {
        float2 gi = unpack2(acc[0][rp]);
        float2 gf = unpack2(acc[1][rp]);
        float2 gg = unpack2(acc[2][rp]);
        float2 go = unpack2(acc[3][rp]);
        {
            int r = 2 * rp;
            float cc = sigm(gf.x) * c[r] + sigm(gi.x) * tanh_(gg.x);
            c[r] = cc;
            hnew[r] = sigm(go.x) * tanh_(cc);
        }
        {
            int r = 2 * rp + 1;
            float cc = sigm(gf.y) * c[r] + sigm(gi.y) * tanh_(gg.y);
            c[r] = cc;
            hnew[r] = sigm(go.y) * tanh_(cc);
        }
    }
}

__global__ void __launch_bounds__(NT, 1)
decoder_kernel(const float* __restrict__ z,
               const float* __restrict__ w_lh, const float* __restrict__ b_lh,
               const float* __restrict__ w_lc, const float* __restrict__ b_lc,
               const float* __restrict__ w_ih0, const float* __restrict__ w_hh0,
               const float* __restrict__ b_ih0, const float* __restrict__ b_hh0,
               const float* __restrict__ w_ih1, const float* __restrict__ w_hh1,
               const float* __restrict__ b_ih1, const float* __restrict__ b_hh1,
               const float* __restrict__ w_proj, const float* __restrict__ b_proj,
               float* __restrict__ out) {
    __shared__ __align__(16) float h0_s[HID * RP];
    __shared__ __align__(16) float h1_s[HID * RP];
    __shared__ __align__(16) float x_s[DIM * RP];
    __shared__ __align__(16) float z_s[ROWS * LATD];

    const int tid = threadIdx.x;
    const int r0  = blockIdx.x * ROWS;

    // ---- load z slab, zero x0 ----
    for (int i = tid; i < ROWS * LATD; i += NT)
        z_s[i] = z[(size_t)(r0 + i / LATD) * LATD + (i % LATD)];
    for (int i = tid; i < DIM * RP; i += NT) x_s[i] = 0.f;
    __syncthreads();

    // ---- init h/c : h_init = z @ w_lh^T + b_lh ; reshape(B,2,H) -> [:,0]=units 0..255 ----
    float c0r[ROWS], c1r[ROWS];
    {
        float h0v[ROWS], h1v[ROWS];
        #pragma unroll
        for (int r = 0; r < ROWS; ++r) {
            h0v[r] = b_lh[tid];       h1v[r] = b_lh[HID + tid];
            c0r[r] = b_lc[tid];       c1r[r] = b_lc[HID + tid];
        }
        const float* wl0 = w_lh + (size_t)tid * LATD;
        const float* wl1 = w_lh + (size_t)(HID + tid) * LATD;
        const float* wc0 = w_lc + (size_t)tid * LATD;
        const float* wc1 = w_lc + (size_t)(HID + tid) * LATD;
        for (int k = 0; k < LATD; ++k) {
            float a0 = wl0[k], a1 = wl1[k], a2 = wc0[k], a3 = wc1[k];
            #pragma unroll
            for (int r = 0; r < ROWS; ++r) {
                float zv = z_s[r * LATD + k];
                h0v[r] = fmaf(zv, a0, h0v[r]);
                h1v[r] = fmaf(zv, a1, h1v[r]);
                c0r[r] = fmaf(zv, a2, c0r[r]);
                c1r[r] = fmaf(zv, a3, c1r[r]);
            }
        }
        #pragma unroll
        for (int r = 0; r < ROWS; ++r) {
            h0_s[tid * RP + r] = h0v[r];
            h1_s[tid * RP + r] = h1v[r];
        }
    }

    // ---- fused gate biases (b_ih + b_hh), per owned hidden unit ----
    float bias0[4], bias1[4];
    #pragma unroll
    for (int g = 0; g < 4; ++g) {
        bias0[g] = b_ih0[g * HID + tid] + b_hh0[g * HID + tid];
        bias1[g] = b_ih1[g * HID + tid] + b_hh1[g * HID + tid];
    }

    // ---- projection task mapping: 160 threads, (d, row-pair) ----
    const int pd  = tid % DIM;   // 0..19
    const int prp = tid / DIM;   // 0..7 when tid<160
    const float pbias = b_proj[pd];

    __syncthreads();

    // =============================== time loop ===============================
    for (int t = 0; t < TSTEPS; ++t) {
        unsigned long long acc[4][8];
        float hnew[ROWS];

        // ---- layer 0: gates = x @ w_ih0^T + h0 @ w_hh0^T + bias ----
        #pragma unroll
        for (int g = 0; g < 4; ++g) {
            unsigned long long bd = dup2(bias0[g]);
            #pragma unroll
            for (int rp = 0; rp < 8; ++rp) acc[g][rp] = bd;
        }
        gemm_gates<DIM>(w_ih0, x_s, tid, acc);
        gemm_gates<HID>(w_hh0, h0_s, tid, acc);
        cell_update(acc, c0r, hnew);
        __syncthreads();                       // all readers of old h0 done
        #pragma unroll
        for (int r = 0; r < ROWS; ++r) h0_s[tid * RP + r] = hnew[r];
        __syncthreads();                       // new h0 visible

        // ---- layer 1: gates = h0 @ w_ih1^T + h1 @ w_hh1^T + bias ----
        #pragma unroll
        for (int g = 0; g < 4; ++g) {
            unsigned long long bd = dup2(bias1[g]);
            #pragma unroll
            for (int rp = 0; rp < 8; ++rp) acc[g][rp] = bd;
        }
        gemm_gates<HID>(w_ih1, h0_s, tid, acc);
        gemm_gates<HID>(w_hh1, h1_s, tid, acc);
        cell_update(acc, c1r, hnew);
        __syncthreads();                       // all readers of old h1 done
        #pragma unroll
        for (int r = 0; r < ROWS; ++r) h1_s[tid * RP + r] = hnew[r];
        __syncthreads();                       // new h1 visible

        // ---- projection: y = h1 @ w_proj^T + b_proj ; feed back as next x ----
        if (tid < DIM * 8) {
            unsigned long long pa = dup2(pbias);
            const float* wp = w_proj + (size_t)pd * HID;
            #pragma unroll 4
            for (int k4 = 0; k4 < HID / 4; ++k4) {
                float4 wv = __ldg(reinterpret_cast<const float4*>(wp) + k4);
                float ws[4] = {wv.x, wv.y, wv.z, wv.w};
                #pragma unroll
                for (int kk = 0; kk < 4; ++kk) {
                    unsigned long long h2 = *reinterpret_cast<const unsigned long long*>(
                        h1_s + (4 * k4 + kk) * RP + 2 * prp);
                    pa = fma2(h2, dup2(ws[kk]), pa);
                }
            }
            float2 y = unpack2(pa);
            int r = 2 * prp;
            out[(size_t)(r0 + r)     * TSTEPS * DIM + (size_t)t * DIM + pd] = y.x;
            out[(size_t)(r0 + r + 1) * TSTEPS * DIM + (size_t)t * DIM + pd] = y.y;
            x_s[pd * RP + r]     = y.x;
            x_s[pd * RP + r + 1] = y.y;
        }
        __syncthreads();                       // next x visible for t+1
    }
}

extern "C" void kernel_launch(void* const* d_in, const int* in_sizes, int n_in,
                              void* d_out, int out_size) {
    // Input order: z, target_lengths, [max_len], w_lh, b_lh, w_lc, b_lc,
    //              w_ih0, w_hh0, b_ih0, b_hh0, w_ih1, w_hh1, b_ih1, b_hh1, w_proj, b_proj
    // max_len is a Python int in the reference; it may or may not be materialized
    // as a device input. Detect via input count.
    const int wbase = (n_in >= 17) ? 3 : 2;

    const float* z      = (const float*)d_in[0];
    const float* w_lh   = (const float*)d_in[wbase + 0];
    const float* b_lh   = (const float*)d_in[wbase + 1];
    const float* w_lc   = (const float*)d_in[wbase + 2];
    const float* b_lc   = (const float*)d_in[wbase + 3];
    const float* w_ih0  = (const float*)d_in[wbase + 4];
    const float* w_hh0  = (const float*)d_in[wbase + 5];
    const float* b_ih0  = (const float*)d_in[wbase + 6];
    const float* b_hh0  = (const float*)d_in[wbase + 7];
    const float* w_ih1  = (const float*)d_in[wbase + 8];
    const float* w_hh1  = (const float*)d_in[wbase + 9];
    const float* b_ih1  = (const float*)d_in[wbase + 10];
    const float* b_hh1  = (const float*)d_in[wbase + 11];
    const float* w_proj = (const float*)d_in[wbase + 12];
    const float* b_proj = (const float*)d_in[wbase + 13];

    decoder_kernel<<<NCTA, NT>>>(z, w_lh, b_lh, w_lc, b_lc,
                                 w_ih0, w_hh0, b_ih0, b_hh0,
                                 w_ih1, w_hh1, b_ih1, b_hh1,
                                 w_proj, b_proj, (float*)d_out);
}

// round 3
// speedup vs baseline: 1.6542x; 1.6542x over previous
#include <cuda_runtime.h>

// Problem constants (fixed by the dataset)
#define BATCH   2048
#define LATD    32
#define HID     256
#define DIM     20
#define TSTEPS  512

#define ROWS    16                 // batch rows per CTA
#define RP      18                 // padded SMEM row stride
#define NCTA    (BATCH / ROWS)     // 128 CTAs
#define NT      256                // threads per CTA (1 thread = 1 hidden unit)

typedef unsigned long long ull;

// ---------------- packed weight scratch (repacked once per launch) ----------------
// Layout: A[k][unit][gate], gate fastest (float4 per (k,unit)).
__device__ float g_A0x[DIM * 4 * HID];     // from w_ih0 [4H x D]
__device__ float g_A0h[HID * 4 * HID];     // from w_hh0 [4H x H]
__device__ float g_A1x[HID * 4 * HID];     // from w_ih1 [4H x H]
__device__ float g_A1h[HID * 4 * HID];     // from w_hh1 [4H x H]
__device__ float g_PT [HID * DIM];         // w_proj^T: PT[k][d]

// ---------------- packed fp32x2 helpers ----------------
__device__ __forceinline__ ull dup2(float w) {
    ull d; asm("mov.b64 %0, {%1, %1};" : "=l"(d) : "f"(w)); return d;
}
__device__ __forceinline__ ull fma2(ull a, ull b, ull c) {
    ull d; asm("fma.rn.f32x2 %0, %1, %2, %3;" : "=l"(d) : "l"(a), "l"(b), "l"(c)); return d;
}
__device__ __forceinline__ float2 unpack2(ull v) {
    float2 f; asm("mov.b64 {%0, %1}, %2;" : "=f"(f.x), "=f"(f.y) : "l"(v)); return f;
}

// ---------------- saturation-safe fast transcendentals ----------------
__device__ __forceinline__ float sigm(float x) {
    return __fdividef(1.f, 1.f + __expf(-x));
}
__device__ __forceinline__ float tanh_(float x) {
    float e = __expf(2.f * x);
    return 1.f - __fdividef(2.f, e + 1.f);
}

// ---------------- weight repack kernel (runs every launch; deterministic) ----------------
__global__ void repack_kernel(const float* __restrict__ w_ih0,
                              const float* __restrict__ w_hh0,
                              const float* __restrict__ w_ih1,
                              const float* __restrict__ w_hh1,
                              const float* __restrict__ w_proj) {
    const int stride = gridDim.x * blockDim.x;
    const int base   = blockIdx.x * blockDim.x + threadIdx.x;
    // A0x : [D][HID][4]  <- w_ih0[(g*HID+u)*D + k]
    for (int idx = base; idx < DIM * HID * 4; idx += stride) {
        int k = idx / (HID * 4), ug = idx % (HID * 4), u = ug >> 2, g = ug & 3;
        g_A0x[idx] = w_ih0[(g * HID + u) * DIM + k];
    }
    // A0h / A1x / A1h : [HID][HID][4]
    for (int idx = base; idx < HID * HID * 4; idx += stride) {
        int k = idx / (HID * 4), ug = idx % (HID * 4), u = ug >> 2, g = ug & 3;
        int src = (g * HID + u) * HID + k;
        g_A0h[idx] = w_hh0[src];
        g_A1x[idx] = w_ih1[src];
        g_A1h[idx] = w_hh1[src];
    }
    // PT : [HID][DIM] <- w_proj[d*HID + k]
    for (int idx = base; idx < HID * DIM; idx += stride) {
        int k = idx / DIM, d = idx % DIM;
        g_PT[idx] = w_proj[d * HID + k];
    }
}

// ---------------- gate GEMM with coalesced packed weights ----------------
// acc[g][rp] += A[k][tid][g] * hs[k][2rp..2rp+1]
template <int K>
__device__ __forceinline__ void gemm_packed(const float* __restrict__ wp,
                                            const float* __restrict__ hs,
                                            int tid, ull (&acc)[4][8]) {
    const float4* wv = reinterpret_cast<const float4*>(wp) + tid;
    #pragma unroll 4
    for (int k = 0; k < K; ++k) {
        float4 w4 = __ldg(wv + (size_t)k * HID);     // 1 LDG.128, fully coalesced per warp
        const float* hp = hs + k * RP;
        ull h2[8];
        #pragma unroll
        for (int rp = 0; rp < 8; ++rp)
            h2[rp] = *reinterpret_cast<const ull*>(hp + 2 * rp);
        ull w0 = dup2(w4.x), w1 = dup2(w4.y), w2 = dup2(w4.z), w3 = dup2(w4.w);
        #pragma unroll
        for (int rp = 0; rp < 8; ++rp) {
            acc[0][rp] = fma2(h2[rp], w0, acc[0][rp]);
            acc[1][rp] = fma2(h2[rp], w1, acc[1][rp]);
            acc[2][rp] = fma2(h2[rp], w2, acc[2][rp]);
            acc[3][rp] = fma2(h2[rp], w3, acc[3][rp]);
        }
    }
}

__device__ __forceinline__ void cell_update(ull (&acc)[4][8],
                                            float (&c)[ROWS], float (&hnew)[ROWS]) {
    #pragma unroll
    for (int rp = 0; rp < 8; ++rp) {
        float2 gi = unpack2(acc[0][rp]);
        float2 gf = unpack2(acc[1][rp]);
        float2 gg = unpack2(acc[2][rp]);
        float2 go = unpack2(acc[3][rp]);
        {
            int r = 2 * rp;
            float cc = sigm(gf.x) * c[r] + sigm(gi.x) * tanh_(gg.x);
            c[r] = cc;  hnew[r] = sigm(go.x) * tanh_(cc);
        }
        {
            int r = 2 * rp + 1;
            float cc = sigm(gf.y) * c[r] + sigm(gi.y) * tanh_(gg.y);
            c[r] = cc;  hnew[r] = sigm(go.y) * tanh_(cc);
        }
    }
}

__global__ void __launch_bounds__(NT, 1)
decoder_kernel(const float* __restrict__ z,
               const float* __restrict__ w_lh, const float* __restrict__ b_lh,
               const float* __restrict__ w_lc, const float* __restrict__ b_lc,
               const float* __restrict__ b_ih0, const float* __restrict__ b_hh0,
               const float* __restrict__ b_ih1, const float* __restrict__ b_hh1,
               const float* __restrict__ b_proj,
               float* __restrict__ out) {
    __shared__ __align__(16) float h0_s[HID * RP];
    __shared__ __align__(16) float h1_s[HID * RP];
    __shared__ __align__(16) float x_s[DIM * RP];
    __shared__ __align__(16) float z_s[ROWS * LATD];

    const int tid = threadIdx.x;
    const int r0  = blockIdx.x * ROWS;

    // ---- load z slab, zero x0 ----
    for (int i = tid; i < ROWS * LATD; i += NT)
        z_s[i] = z[(size_t)(r0 + i / LATD) * LATD + (i % LATD)];
    for (int i = tid; i < DIM * RP; i += NT) x_s[i] = 0.f;
    __syncthreads();

    // ---- init h/c : h_init = z @ w_lh^T + b_lh ; reshape(B,2,H) ----
    float c0r[ROWS], c1r[ROWS];
    {
        float h0v[ROWS], h1v[ROWS];
        #pragma unroll
        for (int r = 0; r < ROWS; ++r) {
            h0v[r] = b_lh[tid];  h1v[r] = b_lh[HID + tid];
            c0r[r] = b_lc[tid];  c1r[r] = b_lc[HID + tid];
        }
        const float* wl0 = w_lh + (size_t)tid * LATD;
        const float* wl1 = w_lh + (size_t)(HID + tid) * LATD;
        const float* wc0 = w_lc + (size_t)tid * LATD;
        const float* wc1 = w_lc + (size_t)(HID + tid) * LATD;
        for (int k = 0; k < LATD; ++k) {
            float a0 = wl0[k], a1 = wl1[k], a2 = wc0[k], a3 = wc1[k];
            #pragma unroll
            for (int r = 0; r < ROWS; ++r) {
                float zv = z_s[r * LATD + k];
                h0v[r] = fmaf(zv, a0, h0v[r]);
                h1v[r] = fmaf(zv, a1, h1v[r]);
                c0r[r] = fmaf(zv, a2, c0r[r]);
                c1r[r] = fmaf(zv, a3, c1r[r]);
            }
        }
        #pragma unroll
        for (int r = 0; r < ROWS; ++r) {
            h0_s[tid * RP + r] = h0v[r];
            h1_s[tid * RP + r] = h1v[r];
        }
    }

    // ---- fused gate biases ----
    float bias0[4], bias1[4];
    #pragma unroll
    for (int g = 0; g < 4; ++g) {
        bias0[g] = b_ih0[g * HID + tid] + b_hh0[g * HID + tid];
        bias1[g] = b_ih1[g * HID + tid] + b_hh1[g * HID + tid];
    }

    // ---- projection task mapping ----
    const int pd  = tid % DIM;   // 0..19
    const int prp = tid / DIM;   // 0..7 when tid<160
    const float pbias = b_proj[pd];

    __syncthreads();

    // =============================== time loop ===============================
    for (int t = 0; t < TSTEPS; ++t) {
        ull acc[4][8];
        float hnew[ROWS];

        // ---- layer 0 ----
        #pragma unroll
        for (int g = 0; g < 4; ++g) {
            ull bd = dup2(bias0[g]);
            #pragma unroll
            for (int rp = 0; rp < 8; ++rp) acc[g][rp] = bd;
        }
        gemm_packed<DIM>(g_A0x, x_s, tid, acc);
        gemm_packed<HID>(g_A0h, h0_s, tid, acc);
        cell_update(acc, c0r, hnew);
        __syncthreads();
        #pragma unroll
        for (int r = 0; r < ROWS; ++r) h0_s[tid * RP + r] = hnew[r];
        __syncthreads();

        // ---- layer 1 ----
        #pragma unroll
        for (int g = 0; g < 4; ++g) {
            ull bd = dup2(bias1[g]);
            #pragma unroll
            for (int rp = 0; rp < 8; ++rp) acc[g][rp] = bd;
        }
        gemm_packed<HID>(g_A1x, h0_s, tid, acc);
        gemm_packed<HID>(g_A1h, h1_s, tid, acc);
        cell_update(acc, c1r, hnew);
        __syncthreads();
        #pragma unroll
        for (int r = 0; r < ROWS; ++r) h1_s[tid * RP + r] = hnew[r];
        __syncthreads();

        // ---- projection: y = h1 @ w_proj^T + b_proj ; feed back ----
        if (tid < DIM * 8) {
            ull pa = dup2(pbias);
            #pragma unroll 4
            for (int k = 0; k < HID; ++k) {
                float wv = __ldg(g_PT + k * DIM + pd);   // coalesced over lanes
                ull h2 = *reinterpret_cast<const ull*>(h1_s + k * RP + 2 * prp);
                pa = fma2(h2, dup2(wv), pa);
            }
            float2 y = unpack2(pa);
            int r = 2 * prp;
            out[(size_t)(r0 + r)     * TSTEPS * DIM + (size_t)t * DIM + pd] = y.x;
            out[(size_t)(r0 + r + 1) * TSTEPS * DIM + (size_t)t * DIM + pd] = y.y;
            x_s[pd * RP + r]     = y.x;
            x_s[pd * RP + r + 1] = y.y;
        }
        __syncthreads();
    }
}

extern "C" void kernel_launch(void* const* d_in, const int* in_sizes, int n_in,
                              void* d_out, int out_size) {
    const int wbase = (n_in >= 17) ? 3 : 2;

    const float* z      = (const float*)d_in[0];
    const float* w_lh   = (const float*)d_in[wbase + 0];
    const float* b_lh   = (const float*)d_in[wbase + 1];
    const float* w_lc   = (const float*)d_in[wbase + 2];
    const float* b_lc   = (const float*)d_in[wbase + 3];
    const float* w_ih0  = (const float*)d_in[wbase + 4];
    const float* w_hh0  = (const float*)d_in[wbase + 5];
    const float* b_ih0  = (const float*)d_in[wbase + 6];
    const float* b_hh0  = (const float*)d_in[wbase + 7];
    const float* w_ih1  = (const float*)d_in[wbase + 8];
    const float* w_hh1  = (const float*)d_in[wbase + 9];
    const float* b_ih1  = (const float*)d_in[wbase + 10];
    const float* b_hh1  = (const float*)d_in[wbase + 11];
    const float* w_proj = (const float*)d_in[wbase + 12];
    const float* b_proj = (const float*)d_in[wbase + 13];

    repack_kernel<<<256, 256>>>(w_ih0, w_hh0, w_ih1, w_hh1, w_proj);
    decoder_kernel<<<NCTA, NT>>>(z, w_lh, b_lh, w_lc, b_lc,
                                 b_ih0, b_hh0, b_ih1, b_hh1,
                                 b_proj, (float*)d_out);
}